// round 2
// baseline (speedup 1.0000x reference)
#include <cuda_runtime.h>
#include <cstdint>

#define C 19
#define DF 256
#define DF4 64
#define NPIX_MAX 262144

// ---------------- scratch (device globals; no runtime allocation) ----------------
__device__ float g_sums[C * DF];
__device__ float g_denom[C];
__device__ __align__(16) float g_cent[C * DF];
__device__ unsigned g_seen;
__device__ int g_src_count;
__device__ int g_src_list[NPIX_MAX];
__device__ double g_total;
__device__ double g_ws;

typedef unsigned long long ull;

union F4U { float4 f; ulonglong2 u; };
union U2F { ull u; float2 f; };

__device__ __forceinline__ void fma2(ull& d, ull a, ull b) {
    asm("fma.rn.f32x2 %0, %1, %2, %0;" : "+l"(d) : "l"(a), "l"(b));
}

// ---------------- K0: zero scratch (must run every replay) ----------------
__global__ void k0_zero() {
    int t = threadIdx.x;
    for (int i = t; i < C * DF; i += 256) g_sums[i] = 0.f;
    if (t < C) g_denom[t] = 0.f;
    if (t == 0) { g_total = 0.0; g_ws = 0.0; g_src_count = 0; g_seen = 0u; }
}

// ---------------- K1: segment sums + denoms + source compaction ----------------
#define K1_T 128
#define K1_TILE 256

__global__ void __launch_bounds__(K1_T) k1_segment(
    const float* __restrict__ sfeat, const float* __restrict__ tfeat,
    const float* __restrict__ conf, const int* __restrict__ sarg,
    const int* __restrict__ targ, const int* __restrict__ smask, int N)
{
    __shared__ float acc[C * 128];
    __shared__ float shw[K1_TILE];
    __shared__ int   shc[K1_TILE];
    __shared__ float sden[C];
    __shared__ float swsum[K1_T / 32];

    const int t = threadIdx.x;
    const int half = blockIdx.x & 1;
    const int chunk = blockIdx.x >> 1;
    const int nch = gridDim.x >> 1;
    const long total = 2L * (long)N;
    const long per = (total + nch - 1) / nch;
    const long p0 = (long)chunk * per;
    long p1 = p0 + per; if (p1 > total) p1 = total;

    for (int i = t; i < C * 128; i += K1_T) acc[i] = 0.f;
    if (t < C) sden[t] = 0.f;
    float wsl = 0.f;
    __syncthreads();

    const int dbase = half * 128 + t;

    for (long base = p0; base < p1; base += K1_TILE) {
        // ---- stage 256 pixel descriptors (class, weight) ----
        #pragma unroll
        for (int r = 0; r < K1_TILE / K1_T; r++) {
            int j = t + r * K1_T;
            long i = base + j;
            int c = 0; float w = 0.f; int srcflag = 0;
            if (i < p1) {
                if (i < (long)N) {                       // source domain
                    c = sarg[i];
                    w = (smask[i] != 0) ? 1.f : 0.f;
                    srcflag = (w > 0.f);
                } else {                                 // target domain
                    c = targ[i - N];
                    w = 1.f - conf[i - N];
                }
            }
            shc[j] = c; shw[j] = w;
            if (half == 0) {
                if (w > 0.f) atomicAdd(&sden[c], w);
                if (srcflag) wsl += 1.f;
                // warp-ballot compaction of live source pixel indices
                unsigned bal = __ballot_sync(0xffffffffu, srcflag);
                int cnt = __popc(bal);
                int bbase = 0;
                if ((t & 31) == 0 && cnt) bbase = atomicAdd(&g_src_count, cnt);
                bbase = __shfl_sync(0xffffffffu, bbase, 0);
                if (srcflag) {
                    int rank = __popc(bal & ((1u << (t & 31)) - 1u));
                    g_src_list[bbase + rank] = (int)i;
                }
            }
        }
        __syncthreads();

        // ---- main accumulation: thread t owns dim (half*128 + t) ----
        int cnt = (int)((p1 - base < (long)K1_TILE) ? (p1 - base) : (long)K1_TILE);
        int j = 0;
        for (; j + 4 <= cnt; j += 4) {
            float w0 = shw[j+0], w1 = shw[j+1], w2 = shw[j+2], w3 = shw[j+3];
            int   c0 = shc[j+0], c1 = shc[j+1], c2 = shc[j+2], c3 = shc[j+3];
            long i0 = base + j;
            const float* r0 = (i0+0 < N) ? sfeat + (i0+0)*DF : tfeat + (i0+0-N)*DF;
            const float* r1 = (i0+1 < N) ? sfeat + (i0+1)*DF : tfeat + (i0+1-N)*DF;
            const float* r2 = (i0+2 < N) ? sfeat + (i0+2)*DF : tfeat + (i0+2-N)*DF;
            const float* r3 = (i0+3 < N) ? sfeat + (i0+3)*DF : tfeat + (i0+3-N)*DF;
            float v0 = 0.f, v1 = 0.f, v2 = 0.f, v3 = 0.f;
            if (w0 != 0.f) v0 = __ldg(r0 + dbase);
            if (w1 != 0.f) v1 = __ldg(r1 + dbase);
            if (w2 != 0.f) v2 = __ldg(r2 + dbase);
            if (w3 != 0.f) v3 = __ldg(r3 + dbase);
            if (w0 != 0.f) acc[c0*128 + t] += w0 * v0;
            if (w1 != 0.f) acc[c1*128 + t] += w1 * v1;
            if (w2 != 0.f) acc[c2*128 + t] += w2 * v2;
            if (w3 != 0.f) acc[c3*128 + t] += w3 * v3;
        }
        for (; j < cnt; j++) {
            float w = shw[j];
            if (w != 0.f) {
                long i = base + j;
                const float* r = (i < N) ? sfeat + i*DF : tfeat + (i-N)*DF;
                acc[shc[j]*128 + t] += w * __ldg(r + dbase);
            }
        }
        __syncthreads();
    }

    // ---- flush block partials ----
    #pragma unroll
    for (int c = 0; c < C; c++) atomicAdd(&g_sums[c*DF + dbase], acc[c*128 + t]);

    if (half == 0) {
        if (t < C) atomicAdd(&g_denom[t], sden[t]);
        #pragma unroll
        for (int o = 16; o; o >>= 1) wsl += __shfl_down_sync(0xffffffffu, wsl, o);
        if ((t & 31) == 0) swsum[t >> 5] = wsl;
        __syncthreads();
        if (t == 0) {
            float s = 0.f;
            #pragma unroll
            for (int w = 0; w < K1_T/32; w++) s += swsum[w];
            atomicAdd(&g_ws, (double)s);
        }
    }
}

// ---------------- K2: centroids + seen mask ----------------
__global__ void k2_centroids(float* __restrict__ out) {
    int c = blockIdx.x, d = threadIdx.x;
    float den = g_denom[c];
    bool seen = den > 0.f;
    float s = g_sums[c*DF + d];
    float cent = seen ? s / fmaxf(den, 1e-12f) : __int_as_float(0x7f800000);
    out[c*DF + d] = cent;
    g_cent[c*DF + d] = seen ? cent : 0.f;
    if (c == 0 && d == 0) {
        unsigned m = 0;
        for (int k = 0; k < C; k++) if (g_denom[k] > 0.f) m |= (1u << k);
        g_seen = m;
    }
}

// ---------------- K3: similarity GEMM + masked entropy reduction ----------------
__global__ void __launch_bounds__(256, 1) k3_entropy(
    const float* __restrict__ sfeat, const float* __restrict__ tfeat,
    const float* __restrict__ conf, int N)
{
    __shared__ float4 scent[C * DF4];
    __shared__ float bsum[8];
    const int t = threadIdx.x;
    for (int i = t; i < C * DF4; i += 256) scent[i] = ((const float4*)g_cent)[i];
    const unsigned seen = g_seen;
    const int M = g_src_count;
    __syncthreads();

    const int E = N + M;                 // target entries then compacted source entries
    const int lane = t & 31, warp = t >> 5;
    const int g = lane >> 2, sub = lane & 3;   // 4-lane groups, 2 entries per group
    float partial = 0.f;

    const int ntiles = (E + 127) >> 7;   // 128 entries per block-tile
    for (int tile = blockIdx.x; tile < ntiles; tile += gridDim.x) {
        const float4* rowp[2]; float w[2];
        #pragma unroll
        for (int p = 0; p < 2; p++) {
            int e = (tile << 7) + warp * 16 + g + p * 8;
            if (e < N)      { rowp[p] = (const float4*)(tfeat + (size_t)e * DF); w[p] = 1.f - __ldg(conf + e); }
            else if (e < E) { int r = g_src_list[e - N]; rowp[p] = (const float4*)(sfeat + (size_t)r * DF); w[p] = 1.f; }
            else            { rowp[p] = (const float4*)tfeat; w[p] = 0.f; }
        }

        ull acc[2][C];
        #pragma unroll
        for (int p = 0; p < 2; p++)
            #pragma unroll
            for (int c = 0; c < C; c++) acc[p][c] = 0ull;

        // each lane covers dims [k*16 + sub*4 .. +4) -> group covers 64B/row contiguous
        #pragma unroll 4
        for (int k = 0; k < 16; k++) {
            const int q = (k << 2) + sub;
            F4U fa, fb;
            fa.f = __ldg(rowp[0] + q);
            fb.f = __ldg(rowp[1] + q);
            #pragma unroll
            for (int c = 0; c < C; c++) {
                F4U cc; cc.f = scent[c * DF4 + q];
                fma2(acc[0][c], fa.u.x, cc.u.x);
                fma2(acc[0][c], fa.u.y, cc.u.y);
                fma2(acc[1][c], fb.u.x, cc.u.x);
                fma2(acc[1][c], fb.u.y, cc.u.y);
            }
        }

        #pragma unroll
        for (int p = 0; p < 2; p++) {
            float z[C];
            #pragma unroll
            for (int c = 0; c < C; c++) {
                U2F cv; cv.u = acc[p][c];
                float s = cv.f.x + cv.f.y;
                s += __shfl_xor_sync(0xffffffffu, s, 1);
                s += __shfl_xor_sync(0xffffffffu, s, 2);
                z[c] = s;
            }
            float m = -3.4e38f;
            #pragma unroll
            for (int c = 0; c < C; c++) if ((seen >> c) & 1u) m = fmaxf(m, z[c]);
            float S = 0.f, U = 0.f;
            #pragma unroll
            for (int c = 0; c < C; c++) if ((seen >> c) & 1u) {
                float e = __expf(z[c] - m);
                S += e;
                U = fmaf(z[c], e, U);
            }
            float ent = U / S - m - __logf(S);   // = sum_c p*logp over seen classes
            partial += (sub == 0 ? w[p] : 0.f) * ent;
        }
    }

    #pragma unroll
    for (int o = 16; o; o >>= 1) partial += __shfl_down_sync(0xffffffffu, partial, o);
    if (lane == 0) bsum[warp] = partial;
    __syncthreads();
    if (t == 0) {
        float s = 0.f;
        #pragma unroll
        for (int wp = 0; wp < 8; wp++) s += bsum[wp];
        atomicAdd(&g_total, (double)s);
    }
}

// ---------------- K4: finalize loss ----------------
__global__ void k4_final(float* __restrict__ out, int N) {
    out[C * DF] = (float)(-(g_total / (g_ws + (double)N)));
}

// ---------------- launch ----------------
extern "C" void kernel_launch(void* const* d_in, const int* in_sizes, int n_in,
                              void* d_out, int out_size) {
    const float* sfeat = (const float*)d_in[0];
    const float* tfeat = (const float*)d_in[1];
    const float* conf  = (const float*)d_in[2];
    const int*   sarg  = (const int*)d_in[3];
    const int*   targ  = (const int*)d_in[4];
    const int*   smask = (const int*)d_in[5];
    float* out = (float*)d_out;
    int N = in_sizes[2];   // target_conf element count = N_PIX

    k0_zero<<<1, 256>>>();
    k1_segment<<<512, K1_T>>>(sfeat, tfeat, conf, sarg, targ, smask, N);
    k2_centroids<<<C, DF>>>(out);
    k3_entropy<<<296, 256>>>(sfeat, tfeat, conf, N);
    k4_final<<<1, 1>>>(out, N);
}

// round 3
// speedup vs baseline: 1.3170x; 1.3170x over previous
#include <cuda_runtime.h>
#include <cstdint>

#define C 19
#define DF 256
#define NPIX_MAX 262144

// ---------------- scratch (device globals; no runtime allocation) ----------------
__device__ float g_sums[C * DF];
__device__ float g_denom[C];
__device__ __align__(16) float g_cent[C * DF];
__device__ unsigned g_seen;
__device__ int g_src_count;
__device__ int g_src_list[NPIX_MAX];
__device__ double g_total;
__device__ double g_ws;

typedef unsigned long long ull;

union F4U { float4 f; ulonglong2 u; };
union U2F { ull u; float2 f; };

__device__ __forceinline__ void fma2(ull& d, ull a, ull b) {
    asm("fma.rn.f32x2 %0, %1, %2, %0;" : "+l"(d) : "l"(a), "l"(b));
}

// ---------------- K0: zero scratch (must run every replay) ----------------
__global__ void k0_zero() {
    int t = threadIdx.x;
    for (int i = t; i < C * DF; i += 256) g_sums[i] = 0.f;
    if (t < C) g_denom[t] = 0.f;
    if (t == 0) { g_total = 0.0; g_ws = 0.0; g_src_count = 0; g_seen = 0u; }
}

// ---------------- K1a: denominators + ws + source compaction (metadata only) ----
#define K1A_BLOCKS 256
__global__ void __launch_bounds__(256) k1a_meta(
    const float* __restrict__ conf, const int* __restrict__ sarg,
    const int* __restrict__ targ, const int* __restrict__ smask, int N)
{
    __shared__ float sden[C];
    __shared__ float swsum[8];
    const int t = threadIdx.x;
    if (t < C) sden[t] = 0.f;
    float wsl = 0.f;
    __syncthreads();

    const int stride = gridDim.x * blockDim.x;
    const int iters = (N + stride - 1) / stride;
    for (int it = 0; it < iters; it++) {
        int i = it * stride + blockIdx.x * blockDim.x + t;
        int active = (i < N);
        // ---- source pixel ----
        int flag = 0;
        if (active) {
            flag = (smask[i] != 0);
            if (flag) { atomicAdd(&sden[sarg[i]], 1.f); wsl += 1.f; }
            float w = 1.f - conf[i];
            atomicAdd(&sden[targ[i]], w);
        }
        // ---- warp-ballot compaction of live source indices ----
        unsigned bal = __ballot_sync(0xffffffffu, flag);
        int cnt = __popc(bal);
        int bbase = 0;
        if ((t & 31) == 0 && cnt) bbase = atomicAdd(&g_src_count, cnt);
        bbase = __shfl_sync(0xffffffffu, bbase, 0);
        if (flag) {
            int rank = __popc(bal & ((1u << (t & 31)) - 1u));
            g_src_list[bbase + rank] = i;
        }
    }

    __syncthreads();
    if (t < C) atomicAdd(&g_denom[t], sden[t]);
    #pragma unroll
    for (int o = 16; o; o >>= 1) wsl += __shfl_down_sync(0xffffffffu, wsl, o);
    if ((t & 31) == 0) swsum[t >> 5] = wsl;
    __syncthreads();
    if (t == 0) {
        float s = 0.f;
        #pragma unroll
        for (int w = 0; w < 8; w++) s += swsum[w];
        atomicAdd(&g_ws, (double)s);
    }
}

// ---------------- K1b: streaming per-class feature sums over live entries -------
#define K1B_BLOCKS 444
__global__ void __launch_bounds__(256) k1b_sums(
    const float* __restrict__ sfeat, const float* __restrict__ tfeat,
    const float* __restrict__ conf, const int* __restrict__ sarg,
    const int* __restrict__ targ, int N)
{
    __shared__ float acc[2][C * DF];   // one copy per 128-thread subgroup
    const int t = threadIdx.x;
    const int sub = t >> 7;            // 0 or 1
    const int l = t & 127;             // dim pair owner: dims [2l, 2l+1]

    for (int i = t; i < 2 * C * DF; i += 256) ((float*)acc)[i] = 0.f;
    __syncthreads();

    const int M = g_src_count;
    const int E = M + N;               // compacted source entries then target entries
    const int sg = blockIdx.x * 2 + sub;
    const int nsg = gridDim.x * 2;

    for (int base = sg * 4; base < E; base += nsg * 4) {
        float2 v[4]; float w[4]; int cc[4];
        #pragma unroll
        for (int u = 0; u < 4; u++) {
            int e = base + u;
            const float2* p = (const float2*)tfeat;
            w[u] = 0.f; cc[u] = 0;
            if (e < M) {
                int r = g_src_list[e];
                p = (const float2*)(sfeat + (size_t)r * DF);
                w[u] = 1.f; cc[u] = sarg[r];
            } else if (e < E) {
                int r = e - M;
                p = (const float2*)(tfeat + (size_t)r * DF);
                w[u] = 1.f - __ldg(conf + r); cc[u] = targ[r];
            }
            v[u] = (w[u] != 0.f) ? __ldg(p + l) : make_float2(0.f, 0.f);
        }
        #pragma unroll
        for (int u = 0; u < 4; u++) {
            if (w[u] != 0.f) {
                float2* a = (float2*)&acc[sub][cc[u] * DF + 2 * l];
                float2 av = *a;
                av.x = fmaf(w[u], v[u].x, av.x);
                av.y = fmaf(w[u], v[u].y, av.y);
                *a = av;
            }
        }
    }

    __syncthreads();
    for (int i = t; i < C * DF; i += 256)
        atomicAdd(&g_sums[i], acc[0][i] + acc[1][i]);
}

// ---------------- K2: centroids + seen mask ----------------
__global__ void k2_centroids(float* __restrict__ out) {
    int c = blockIdx.x, d = threadIdx.x;
    float den = g_denom[c];
    bool seen = den > 0.f;
    float s = g_sums[c * DF + d];
    float cent = seen ? s / fmaxf(den, 1e-12f) : __int_as_float(0x7f800000);
    out[c * DF + d] = cent;
    g_cent[c * DF + d] = seen ? cent : 0.f;
    if (c == 0 && d == 0) {
        unsigned m = 0;
        for (int k = 0; k < C; k++) if (g_denom[k] > 0.f) m |= (1u << k);
        g_seen = m;
    }
}

// ---------------- K3: similarity GEMM + masked entropy reduction ----------------
#define K3_BLOCKS 296
__global__ void __launch_bounds__(256, 2) k3_entropy(
    const float* __restrict__ sfeat, const float* __restrict__ tfeat,
    const float* __restrict__ conf, int N)
{
    __shared__ float4 scent[C * 64];
    __shared__ float bsum[8];
    const int t = threadIdx.x;
    for (int i = t; i < C * 64; i += 256) scent[i] = ((const float4*)g_cent)[i];
    const unsigned seen = g_seen;
    const int M = g_src_count;
    __syncthreads();

    const int E = N + M;                  // target entries then compacted source entries
    const int lane = t & 31, warp = t >> 5;
    const int g = lane >> 3, sub = lane & 7;  // 8-lane groups, 1 entry per group
    float partial = 0.f;

    // 8 warps x 4 groups = 32 entries per block-iteration
    for (int base = blockIdx.x * 32; base < E; base += gridDim.x * 32) {
        const int e = base + warp * 4 + g;
        const bool valid = (e < E);
        const float4* row;
        if (e < N)       row = (const float4*)(tfeat + (size_t)e * DF);
        else if (valid)  row = (const float4*)(sfeat + (size_t)__ldg(g_src_list + (e - N)) * DF);
        else             row = (const float4*)tfeat;

        // full row staged in registers: lane covers dims of float4s {k*8+sub}
        F4U r[8];
        #pragma unroll
        for (int k = 0; k < 8; k++) r[k].f = __ldg(row + k * 8 + sub);

        ull acc[C];
        #pragma unroll
        for (int c = 0; c < C; c++) acc[c] = 0ull;

        #pragma unroll
        for (int k = 0; k < 8; k++) {
            const int q = k * 8 + sub;
            #pragma unroll
            for (int c = 0; c < C; c++) {
                F4U cc; cc.f = scent[c * 64 + q];
                fma2(acc[c], r[k].u.x, cc.u.x);
                fma2(acc[c], r[k].u.y, cc.u.y);
            }
        }

        float z[C];
        #pragma unroll
        for (int c = 0; c < C; c++) {
            U2F cv; cv.u = acc[c];
            float s = cv.f.x + cv.f.y;
            s += __shfl_xor_sync(0xffffffffu, s, 1);
            s += __shfl_xor_sync(0xffffffffu, s, 2);
            s += __shfl_xor_sync(0xffffffffu, s, 4);
            z[c] = s;
        }
        float m = -3.4e38f;
        #pragma unroll
        for (int c = 0; c < C; c++) if ((seen >> c) & 1u) m = fmaxf(m, z[c]);
        float S = 0.f, U = 0.f;
        #pragma unroll
        for (int c = 0; c < C; c++) if ((seen >> c) & 1u) {
            float ex = __expf(z[c] - m);
            S += ex;
            U = fmaf(z[c], ex, U);
        }
        float ent = U / S - m - __logf(S);   // = sum_c p*logp over seen classes

        if (valid && sub == 0) {
            float w = (e < N) ? 1.f - __ldg(conf + e) : 1.f;
            partial += w * ent;
        }
    }

    #pragma unroll
    for (int o = 16; o; o >>= 1) partial += __shfl_down_sync(0xffffffffu, partial, o);
    if (lane == 0) bsum[warp] = partial;
    __syncthreads();
    if (t == 0) {
        float s = 0.f;
        #pragma unroll
        for (int wp = 0; wp < 8; wp++) s += bsum[wp];
        atomicAdd(&g_total, (double)s);
    }
}

// ---------------- K4: finalize loss ----------------
__global__ void k4_final(float* __restrict__ out, int N) {
    out[C * DF] = (float)(-(g_total / (g_ws + (double)N)));
}

// ---------------- launch ----------------
extern "C" void kernel_launch(void* const* d_in, const int* in_sizes, int n_in,
                              void* d_out, int out_size) {
    const float* sfeat = (const float*)d_in[0];
    const float* tfeat = (const float*)d_in[1];
    const float* conf  = (const float*)d_in[2];
    const int*   sarg  = (const int*)d_in[3];
    const int*   targ  = (const int*)d_in[4];
    const int*   smask = (const int*)d_in[5];
    float* out = (float*)d_out;
    int N = in_sizes[2];   // target_conf element count = N_PIX

    k0_zero<<<1, 256>>>();
    k1a_meta<<<K1A_BLOCKS, 256>>>(conf, sarg, targ, smask, N);
    k1b_sums<<<K1B_BLOCKS, 256>>>(sfeat, tfeat, conf, sarg, targ, N);
    k2_centroids<<<C, DF>>>(out);
    k3_entropy<<<K3_BLOCKS, 256>>>(sfeat, tfeat, conf, N);
    k4_final<<<1, 1>>>(out, N);
}

// round 4
// speedup vs baseline: 1.5697x; 1.1918x over previous
#include <cuda_runtime.h>
#include <cstdint>

#define C 19
#define DF 256
#define NPIX_MAX 262144

// ---------------- scratch (device globals; no runtime allocation) ----------------
__device__ float g_sums[C * DF];
__device__ float g_denom[C];
__device__ int g_src_count;
__device__ uint2 g_desc_src[NPIX_MAX];   // {row<<5 | cls, bits(w=1)}
__device__ uint2 g_desc_tgt[NPIX_MAX];   // {row<<5 | cls, bits(1-conf)}
__device__ double g_total;
__device__ double g_ws;

typedef unsigned long long ull;

union F4U { float4 f; ulonglong2 u; };
union U2F { ull u; float2 f; };

__device__ __forceinline__ void fma2(ull& d, ull a, ull b) {
    asm("fma.rn.f32x2 %0, %1, %2, %0;" : "+l"(d) : "l"(a), "l"(b));
}

// ---------------- K0: zero scratch (must run every replay) ----------------
__global__ void k0_zero() {
    int t = threadIdx.x;
    for (int i = t; i < C * DF; i += 256) g_sums[i] = 0.f;
    if (t < C) g_denom[t] = 0.f;
    if (t == 0) { g_total = 0.0; g_ws = 0.0; g_src_count = 0; }
}

// ---------------- K1a: denoms + ws + entry descriptors ----------------
#define K1A_BLOCKS 512
__global__ void __launch_bounds__(256) k1a_meta(
    const float* __restrict__ conf, const int* __restrict__ sarg,
    const int* __restrict__ targ, const int* __restrict__ smask, int N)
{
    __shared__ float sden[C];
    __shared__ float swsum[8];
    const int t = threadIdx.x;
    if (t < C) sden[t] = 0.f;
    float wsl = 0.f;
    __syncthreads();

    const int stride = gridDim.x * blockDim.x;
    const int iters = (N + stride - 1) / stride;
    for (int it = 0; it < iters; it++) {
        int i = it * stride + blockIdx.x * blockDim.x + t;
        int flag = 0, cs = 0;
        if (i < N) {
            flag = (smask[i] != 0);
            cs = sarg[i];
            int ct = targ[i];
            float w = 1.f - conf[i];
            if (flag) { atomicAdd(&sden[cs], 1.f); wsl += 1.f; }
            atomicAdd(&sden[ct], w);
            g_desc_tgt[i] = make_uint2(((unsigned)i << 5) | (unsigned)ct, __float_as_uint(w));
        }
        // warp-ballot compaction of live source entries
        unsigned bal = __ballot_sync(0xffffffffu, flag);
        int cnt = __popc(bal);
        int bbase = 0;
        if ((t & 31) == 0 && cnt) bbase = atomicAdd(&g_src_count, cnt);
        bbase = __shfl_sync(0xffffffffu, bbase, 0);
        if (flag) {
            int rank = __popc(bal & ((1u << (t & 31)) - 1u));
            g_desc_src[bbase + rank] = make_uint2(((unsigned)i << 5) | (unsigned)cs, __float_as_uint(1.f));
        }
    }

    __syncthreads();
    if (t < C) atomicAdd(&g_denom[t], sden[t]);
    #pragma unroll
    for (int o = 16; o; o >>= 1) wsl += __shfl_down_sync(0xffffffffu, wsl, o);
    if ((t & 31) == 0) swsum[t >> 5] = wsl;
    __syncthreads();
    if (t == 0) {
        float s = 0.f;
        #pragma unroll
        for (int w = 0; w < 8; w++) s += swsum[w];
        atomicAdd(&g_ws, (double)s);
    }
}

// ---------------- K1b: streaming per-class feature sums over live entries -------
#define K1B_BLOCKS 740
__global__ void __launch_bounds__(256) k1b_sums(
    const float* __restrict__ sfeat, const float* __restrict__ tfeat, int N)
{
    __shared__ float acc[2][C * DF];   // one copy per 128-thread subgroup
    const int t = threadIdx.x;
    const int sub = t >> 7;            // 0 or 1
    const int l = t & 127;             // dim pair owner: dims [2l, 2l+1]

    for (int i = t; i < 2 * C * DF; i += 256) ((float*)acc)[i] = 0.f;
    __syncthreads();

    const int M = g_src_count;
    const int E = M + N;               // compacted source entries then target entries
    const int sg = blockIdx.x * 2 + sub;
    const int nsg = gridDim.x * 2;

    for (int base = sg * 8; base < E; base += nsg * 8) {
        float2 v[8]; float w[8]; int cls[8];
        #pragma unroll
        for (int u = 0; u < 8; u++) {
            int e = base + u;
            uint2 d; const float2* p;
            if (e < M) {
                d = __ldg(&g_desc_src[e]);
                p = (const float2*)(sfeat + (size_t)(d.x >> 5) * DF);
            } else if (e < E) {
                d = __ldg(&g_desc_tgt[e - M]);
                p = (const float2*)(tfeat + (size_t)(e - M) * DF);
            } else {
                d = make_uint2(0u, 0u);
                p = (const float2*)tfeat;
            }
            cls[u] = (int)(d.x & 31u);
            w[u] = __uint_as_float(d.y);
            v[u] = __ldg(p + l);
        }
        #pragma unroll
        for (int u = 0; u < 8; u++) {
            float2* a = (float2*)&acc[sub][cls[u] * DF + 2 * l];
            float2 av = *a;
            av.x = fmaf(w[u], v[u].x, av.x);
            av.y = fmaf(w[u], v[u].y, av.y);
            *a = av;
        }
    }

    __syncthreads();
    for (int i = t; i < C * DF; i += 256)
        atomicAdd(&g_sums[i], acc[0][i] + acc[1][i]);
}

// ---------------- K3: similarity GEMM + masked entropy reduction ----------------
// Computes centroids block-locally from g_sums/g_denom (so it can run before k2).
#define K3_BLOCKS 296
__global__ void __launch_bounds__(256, 2) k3_entropy(
    const float* __restrict__ sfeat, const float* __restrict__ tfeat, int N)
{
    __shared__ float4 scent[C * 64];
    __shared__ float bsum[8];
    const int t = threadIdx.x;

    // block-local centroid computation (zero for unseen classes)
    for (int i = t; i < C * 64; i += 256) {
        float den = __ldg(&g_denom[i >> 6]);
        float inv = (den > 0.f) ? 1.f / fmaxf(den, 1e-12f) : 0.f;
        float4 s = ((const float4*)g_sums)[i];
        scent[i] = make_float4(s.x * inv, s.y * inv, s.z * inv, s.w * inv);
    }
    unsigned seen = 0;
    #pragma unroll
    for (int c = 0; c < C; c++) if (__ldg(&g_denom[c]) > 0.f) seen |= (1u << c);
    const int M = g_src_count;
    __syncthreads();

    const int E = M + N;                  // compacted source entries then target entries
    const int lane = t & 31, warp = t >> 5;
    const int g = lane >> 3, sub = lane & 7;  // 8-lane groups, 1 entry per group
    float partial = 0.f;

    // 8 warps x 4 groups = 32 entries per block-iteration
    for (int base = blockIdx.x * 32; base < E; base += gridDim.x * 32) {
        const int e = base + warp * 4 + g;
        const float4* row; float w;
        if (e < M) {
            uint2 d = __ldg(&g_desc_src[e]);
            row = (const float4*)(sfeat + (size_t)(d.x >> 5) * DF);
            w = 1.f;
        } else if (e < E) {
            uint2 d = __ldg(&g_desc_tgt[e - M]);
            row = (const float4*)(tfeat + (size_t)(e - M) * DF);
            w = __uint_as_float(d.y);
        } else {
            row = (const float4*)tfeat;
            w = 0.f;
        }

        // full row staged in registers: lane covers float4s {k*8+sub} -> 1 line per warp-load per group
        F4U r[8];
        #pragma unroll
        for (int k = 0; k < 8; k++) r[k].f = __ldg(row + k * 8 + sub);

        ull acc[C];
        #pragma unroll
        for (int c = 0; c < C; c++) acc[c] = 0ull;

        #pragma unroll
        for (int k = 0; k < 8; k++) {
            const int q = k * 8 + sub;
            #pragma unroll
            for (int c = 0; c < C; c++) {
                F4U cc; cc.f = scent[c * 64 + q];
                fma2(acc[c], r[k].u.x, cc.u.x);
                fma2(acc[c], r[k].u.y, cc.u.y);
            }
        }

        float z[C];
        #pragma unroll
        for (int c = 0; c < C; c++) {
            U2F cv; cv.u = acc[c];
            float s = cv.f.x + cv.f.y;
            s += __shfl_xor_sync(0xffffffffu, s, 1);
            s += __shfl_xor_sync(0xffffffffu, s, 2);
            s += __shfl_xor_sync(0xffffffffu, s, 4);
            z[c] = s;
        }
        float m = -3.4e38f;
        #pragma unroll
        for (int c = 0; c < C; c++) if ((seen >> c) & 1u) m = fmaxf(m, z[c]);
        float S = 0.f, U = 0.f;
        #pragma unroll
        for (int c = 0; c < C; c++) if ((seen >> c) & 1u) {
            float ex = __expf(z[c] - m);
            S += ex;
            U = fmaf(z[c], ex, U);
        }
        float ent = U / S - m - __logf(S);   // = sum_c p*logp over seen classes

        if (sub == 0) partial += w * ent;    // w==0 for out-of-range entries
    }

    #pragma unroll
    for (int o = 16; o; o >>= 1) partial += __shfl_down_sync(0xffffffffu, partial, o);
    if (lane == 0) bsum[warp] = partial;
    __syncthreads();
    if (t == 0) {
        float s = 0.f;
        #pragma unroll
        for (int wp = 0; wp < 8; wp++) s += bsum[wp];
        atomicAdd(&g_total, (double)s);
    }
}

// ---------------- K2: write centroid block of the output ----------------
__global__ void k2_centroids(float* __restrict__ out) {
    int c = blockIdx.x, d = threadIdx.x;
    float den = g_denom[c];
    bool seen = den > 0.f;
    float s = g_sums[c * DF + d];
    out[c * DF + d] = seen ? s / fmaxf(den, 1e-12f) : __int_as_float(0x7f800000);
}

// ---------------- K4: finalize loss ----------------
__global__ void k4_final(float* __restrict__ out, int N) {
    out[C * DF] = (float)(-(g_total / (g_ws + (double)N)));
}

// ---------------- launch ----------------
extern "C" void kernel_launch(void* const* d_in, const int* in_sizes, int n_in,
                              void* d_out, int out_size) {
    const float* sfeat = (const float*)d_in[0];
    const float* tfeat = (const float*)d_in[1];
    const float* conf  = (const float*)d_in[2];
    const int*   sarg  = (const int*)d_in[3];
    const int*   targ  = (const int*)d_in[4];
    const int*   smask = (const int*)d_in[5];
    float* out = (float*)d_out;
    int N = in_sizes[2];   // target_conf element count = N_PIX

    k0_zero<<<1, 256>>>();
    k1a_meta<<<K1A_BLOCKS, 256>>>(conf, sarg, targ, smask, N);
    k1b_sums<<<K1B_BLOCKS, 256>>>(sfeat, tfeat, N);
    k3_entropy<<<K3_BLOCKS, 256>>>(sfeat, tfeat, N);   // capture index 3
    k2_centroids<<<C, DF>>>(out);
    k4_final<<<1, 1>>>(out, N);
}